// round 4
// baseline (speedup 1.0000x reference)
#include <cuda_runtime.h>
#include <math.h>

#define NB    32
#define NF    500
#define FEAT  256
#define COUT  2
#define CIN   2
#define KK    16
#define FRAME 160
#define OVL   40
#define NSAMP (NF * FRAME)          // 80000
#define NFILT (COUT * CIN * KK)     // 64

#define GAIN_A 0.69077552789821368f
#define SG     0.50118723362727224f
#define OMSG   0.49881276637272776f

// Partial GEMM results: [split][b*NF+f][o]; o in [0,64)=taps, 64..65=gain logits
__device__ float g_raw[2][(size_t)NB * NF][68];

// ===========================================================================
// Kernel A: K-split GEMM. grid (125, 2); block = 128 rows x 64 cols, K-half
// of 128. Thread tile 8x4. Writes raw partials (no bias/epilogue).
// ===========================================================================
#define TBF 128
#define FS4S 33                      // fs row stride in float4 (132 floats)
#define WSTRIDE 68

__global__ void __launch_bounds__(256) filt_kernel(
    const float* __restrict__ feat,
    const float* __restrict__ ckw,  // (64, 256)
    const float* __restrict__ fgw)  // (2, 256)
{
    extern __shared__ float sm[];
    float*  fs = sm;                              // [128][132]
    float*  Wt = sm + TBF * (FS4S * 4);           // [128][68]
    float4* fs4 = (float4*)fs;
    float4* Wt4 = (float4*)Wt;

    int tid = threadIdx.x;
    int bf0 = blockIdx.x * TBF;
    int s   = blockIdx.y;             // K-split: features [s*128, s*128+128)

    // ---- load feat K-half tile (32 float4 per row) ----
    const float4* feat4 = (const float4*)feat;
    for (int i = tid; i < TBF * 32; i += 256) {
        int r = i >> 5, c4 = i & 31;
        fs4[r * FS4S + c4] = feat4[(size_t)(bf0 + r) * 64 + s * 32 + c4];
    }
    // ---- load W K-half transposed: Wt[fe][o] ----
    for (int i = tid; i < 64 * 128; i += 256) {
        int o = i >> 7, fe = i & 127;
        Wt[fe * WSTRIDE + o] = ckw[(size_t)o * FEAT + s * 128 + fe];
    }
    __syncthreads();

    int ogrp = tid & 15, rgrp = tid >> 4;
    int o0 = ogrp * 4, r0 = rgrp * 8;

    float acc[8][4];
    #pragma unroll
    for (int i = 0; i < 8; ++i)
        #pragma unroll
        for (int j = 0; j < 4; ++j) acc[i][j] = 0.f;

    const float4* fsp = fs4 + r0 * FS4S;
    const float4* wtp = Wt4 + ogrp;               // Wt4 row stride = 17

    #pragma unroll 4
    for (int fe4 = 0; fe4 < 32; ++fe4) {
        float4 fv[8];
        #pragma unroll
        for (int i = 0; i < 8; ++i) fv[i] = fsp[i * FS4S + fe4];
        float4 w0 = wtp[(4 * fe4 + 0) * 17];
        float4 w1 = wtp[(4 * fe4 + 1) * 17];
        float4 w2 = wtp[(4 * fe4 + 2) * 17];
        float4 w3 = wtp[(4 * fe4 + 3) * 17];
        #pragma unroll
        for (int i = 0; i < 8; ++i) {
            acc[i][0] = fmaf(fv[i].x, w0.x, acc[i][0]);
            acc[i][1] = fmaf(fv[i].x, w0.y, acc[i][1]);
            acc[i][2] = fmaf(fv[i].x, w0.z, acc[i][2]);
            acc[i][3] = fmaf(fv[i].x, w0.w, acc[i][3]);
            acc[i][0] = fmaf(fv[i].y, w1.x, acc[i][0]);
            acc[i][1] = fmaf(fv[i].y, w1.y, acc[i][1]);
            acc[i][2] = fmaf(fv[i].y, w1.z, acc[i][2]);
            acc[i][3] = fmaf(fv[i].y, w1.w, acc[i][3]);
            acc[i][0] = fmaf(fv[i].z, w2.x, acc[i][0]);
            acc[i][1] = fmaf(fv[i].z, w2.y, acc[i][1]);
            acc[i][2] = fmaf(fv[i].z, w2.z, acc[i][2]);
            acc[i][3] = fmaf(fv[i].z, w2.w, acc[i][3]);
            acc[i][0] = fmaf(fv[i].w, w3.x, acc[i][0]);
            acc[i][1] = fmaf(fv[i].w, w3.y, acc[i][1]);
            acc[i][2] = fmaf(fv[i].w, w3.z, acc[i][2]);
            acc[i][3] = fmaf(fv[i].w, w3.w, acc[i][3]);
        }
    }

    // ---- gain-logit partial: thread -> (row tid>>1, cout tid&1) ----
    {
        int r = tid >> 1, c = tid & 1;
        const float4* fr = fs4 + r * FS4S;
        const float4* gw = (const float4*)(fgw + (size_t)c * FEAT + s * 128);
        float gsum = 0.f;
        #pragma unroll 4
        for (int q = 0; q < 32; ++q) {
            float4 a = fr[q];
            float4 bq = __ldg(&gw[q]);
            gsum += a.x * bq.x + a.y * bq.y + a.z * bq.z + a.w * bq.w;
        }
        g_raw[s][bf0 + r][64 + c] = gsum;
    }

    // ---- store partials (float4, coalesced across ogrp) ----
    #pragma unroll
    for (int i = 0; i < 8; ++i) {
        float4 v = make_float4(acc[i][0], acc[i][1], acc[i][2], acc[i][3]);
        *(float4*)&g_raw[s][bf0 + r0 + i][o0] = v;
    }
}

// ===========================================================================
// Kernel B: fused epilogue + adaptive conv + overlap-add.
// FPB=4 frames/block, 128 threads, 8 blocks/SM. Prologue builds the 5 needed
// filters from g_raw partials (sum + bias + norm + identity-mix + gain).
// Head: lane = 5 consecutive outputs from a 20-float register window.
// Tail: cooperative — round 1 all lanes (j=lane), round 2 lanes 0-7 (j=32+l),
// exchanged via smem, blended by head lanes 0-7.
// ===========================================================================
#define FPB  4
#define NEED (FPB * FRAME + 16)      // 656
#define XPAD 664

__global__ void __launch_bounds__(FPB * 32, 8) conv_kernel(
    const float* __restrict__ x,     // (B, CIN, NSAMP)
    const float* __restrict__ owin,  // (40,)
    const float* __restrict__ ckb,   // (64,)
    const float* __restrict__ fgb,   // (2,)
    float* __restrict__ out)         // (B, COUT, NSAMP)
{
    __shared__ __align__(16) float xs[CIN][XPAD];
    __shared__ float praw[FPB + 1][68];
    __shared__ __align__(16) float wsm[FPB + 1][NFILT];
    __shared__ float sA[FPB + 1][COUT];            // SG*invn*gain
    __shared__ float sB[FPB + 1][COUT];            // OMSG*gain
    __shared__ float tb[FPB][COUT][OVL];
    __shared__ __align__(16) float ob[FPB][COUT][FRAME];
    __shared__ float w1s[OVL], w2s[OVL];

    const int NT = FPB * 32;
    int f0 = blockIdx.x * FPB;
    int b  = blockIdx.y;
    int tid  = threadIdx.x;
    int lane = tid & 31;
    int w    = tid >> 5;

    // ---- x window (float4 coalesced) ----
    const float* xb = x + (size_t)b * CIN * NSAMP;
    if (f0 == 0) {
        if (tid < 16) { xs[0][tid] = 0.f; xs[1][tid] = 0.f; }
        const int N4 = (NEED - 16) / 4;            // 160
        for (int i = tid; i < CIN * N4; i += NT) {
            int ci = i / N4, q = i - ci * N4;
            ((float4*)(xs[ci] + 16))[q] =
                ((const float4*)(xb + (size_t)ci * NSAMP))[q];
        }
    } else {
        int base = f0 * FRAME - 16;
        const int N4 = NEED / 4;                   // 164
        for (int i = tid; i < CIN * N4; i += NT) {
            int ci = i / N4, q = i - ci * N4;
            ((float4*)xs[ci])[q] =
                ((const float4*)(xb + (size_t)ci * NSAMP + base))[q];
        }
    }

    // ---- epilogue stage 1: combine partials + bias ----
    for (int i = tid; i < (FPB + 1) * 68; i += NT) {
        int fr = i / 68, o = i - fr * 68;
        int fi = f0 - 1 + fr;
        float v = 0.f;
        if (fi >= 0 && o < 66) {
            size_t row = (size_t)b * NF + fi;
            v = g_raw[0][row][o] + g_raw[1][row][o]
              + ((o < 64) ? __ldg(&ckb[o]) : __ldg(&fgb[o - 64]));
        }
        praw[fr][o] = v;
    }
    if (tid < OVL) {
        w2s[tid] = owin[tid];
        w1s[tid] = owin[OVL - 1 - tid];
    }
    __syncthreads();

    // ---- epilogue stage 2: per (frame, cout) norm + gain ----
    if (tid < (FPB + 1) * COUT) {
        int fr = tid >> 1, co = tid & 1;
        int fi = f0 - 1 + fr;
        float ss = 0.f;
        #pragma unroll
        for (int i = 0; i < 32; ++i) {
            float v = praw[fr][co * 32 + i];
            ss += v * v;
        }
        float invn = 1.0f / (1e-6f + sqrtf(ss));
        float gain = (fi >= 0) ? expf(GAIN_A * tanhf(praw[fr][64 + co])) : 0.f;
        sA[fr][co] = SG * invn * gain;
        sB[fr][co] = OMSG * gain;
    }
    __syncthreads();

    // ---- epilogue stage 3: final filters ----
    for (int i = tid; i < (FPB + 1) * NFILT; i += NT) {
        int fr = i >> 6, o = i & 63, co = o >> 5;
        float v = praw[fr][o] * sA[fr][co];
        if ((o & 15) == 7) v += sB[fr][co];        // identity tap k=7
        wsm[fr][o] = v;
    }
    __syncthreads();

    // ================= conv =================
    int j0 = 5 * lane;
    int sb = w * FRAME + 16;

    float a0[5] = {0,0,0,0,0}, a1[5] = {0,0,0,0,0};
    const float4* wc = (const float4*)wsm[w + 1];
    const float4* wp = (const float4*)wsm[w];

    // ---- head ----
    #pragma unroll
    for (int ci = 0; ci < CIN; ++ci) {
        float xw[20];
        #pragma unroll
        for (int i = 0; i < 20; ++i)
            xw[i] = xs[ci][sb + j0 - 15 + i];
        #pragma unroll
        for (int kc = 0; kc < 4; ++kc) {
            float4 c0 = wc[ci * 4 + kc];
            float4 c1 = wc[8 + ci * 4 + kc];
            float wk0[4] = {c0.x, c0.y, c0.z, c0.w};
            float wk1[4] = {c1.x, c1.y, c1.z, c1.w};
            #pragma unroll
            for (int kk = 0; kk < 4; ++kk) {
                int k = 4 * kc + kk;
                #pragma unroll
                for (int m = 0; m < 5; ++m) {
                    float xv = xw[m + 15 - k];
                    a0[m] = fmaf(wk0[kk], xv, a0[m]);
                    a1[m] = fmaf(wk1[kk], xv, a1[m]);
                }
            }
        }
    }

    // ---- tail round 1: j = lane (all 32 lanes useful, j<40 always) ----
    {
        float t0 = 0.f, t1 = 0.f;
        #pragma unroll
        for (int ci = 0; ci < CIN; ++ci) {
            float tw[16];
            #pragma unroll
            for (int i = 0; i < 16; ++i)
                tw[i] = xs[ci][sb + lane - 15 + i];
            #pragma unroll
            for (int kc = 0; kc < 4; ++kc) {
                float4 c0 = wp[ci * 4 + kc];
                float4 c1 = wp[8 + ci * 4 + kc];
                float wk0[4] = {c0.x, c0.y, c0.z, c0.w};
                float wk1[4] = {c1.x, c1.y, c1.z, c1.w};
                #pragma unroll
                for (int kk = 0; kk < 4; ++kk) {
                    int k = 4 * kc + kk;
                    t0 = fmaf(wk0[kk], tw[15 - k], t0);
                    t1 = fmaf(wk1[kk], tw[15 - k], t1);
                }
            }
        }
        tb[w][0][lane] = t0;
        tb[w][1][lane] = t1;
    }
    // ---- tail round 2: j = 32 + lane (lanes 0-7) ----
    if (lane < 8) {
        int j = 32 + lane;
        float t0 = 0.f, t1 = 0.f;
        #pragma unroll
        for (int ci = 0; ci < CIN; ++ci) {
            float tw[16];
            #pragma unroll
            for (int i = 0; i < 16; ++i)
                tw[i] = xs[ci][sb + j - 15 + i];
            #pragma unroll
            for (int kc = 0; kc < 4; ++kc) {
                float4 c0 = wp[ci * 4 + kc];
                float4 c1 = wp[8 + ci * 4 + kc];
                float wk0[4] = {c0.x, c0.y, c0.z, c0.w};
                float wk1[4] = {c1.x, c1.y, c1.z, c1.w};
                #pragma unroll
                for (int kk = 0; kk < 4; ++kk) {
                    int k = 4 * kc + kk;
                    t0 = fmaf(wk0[kk], tw[15 - k], t0);
                    t1 = fmaf(wk1[kk], tw[15 - k], t1);
                }
            }
        }
        tb[w][0][j] = t0;
        tb[w][1][j] = t1;
    }
    __syncwarp();

    // ---- blend + stage ----
    if (lane < 8) {
        #pragma unroll
        for (int m = 0; m < 5; ++m) {
            int j = j0 + m;
            ob[w][0][j] = w1s[j] * a0[m] + w2s[j] * tb[w][0][j];
            ob[w][1][j] = w1s[j] * a1[m] + w2s[j] * tb[w][1][j];
        }
    } else {
        #pragma unroll
        for (int m = 0; m < 5; ++m) {
            int j = j0 + m;
            ob[w][0][j] = a0[m];
            ob[w][1][j] = a1[m];
        }
    }
    __syncwarp();

    // ---- coalesced float4 store ----
    int f = f0 + w;
    #pragma unroll
    for (int co = 0; co < COUT; ++co) {
        float4* op = (float4*)(out + (size_t)b * COUT * NSAMP
                               + (size_t)co * NSAMP + (size_t)f * FRAME);
        const float4* obp = (const float4*)ob[w][co];
        #pragma unroll
        for (int i = lane; i < FRAME / 4; i += 32)
            op[i] = obp[i];
    }
}

extern "C" void kernel_launch(void* const* d_in, const int* in_sizes, int n_in,
                              void* d_out, int out_size)
{
    const float* x    = (const float*)d_in[0];
    const float* feat = (const float*)d_in[1];
    const float* ckw  = (const float*)d_in[2];
    const float* ckb  = (const float*)d_in[3];
    const float* fgw  = (const float*)d_in[4];
    const float* fgb  = (const float*)d_in[5];
    const float* ow   = (const float*)d_in[6];
    float* out = (float*)d_out;

    // filt smem: fs 128*132 + Wt 128*68 floats = 102400 B
    int smem = (TBF * FS4S * 4 + TBF * WSTRIDE) * (int)sizeof(float);
    static int configured = 0;
    if (!configured) {
        cudaFuncSetAttribute(filt_kernel,
                             cudaFuncAttributeMaxDynamicSharedMemorySize, smem);
        configured = 1;
    }

    filt_kernel<<<dim3(NB * NF / TBF, 2), 256, smem>>>(feat, ckw, fgw);
    conv_kernel<<<dim3(NF / FPB, NB), FPB * 32>>>(x, ow, ckb, fgb, out);
}